// round 15
// baseline (speedup 1.0000x reference)
#include <cuda_runtime.h>
#include <cuda_bf16.h>
#include <math.h>
#include <stdint.h>

#define Bsz    4096
#define Dh     256
#define NROW   8192
#define TEMP_INV 10.0f
#define BM     128
#define BN     128
#define BK     32
#define NK     8
#define T32    32
#define NBLK_SYM   528
#define NBLK_TOTAL (3 * NBLK_SYM + 2 * 1024)   // 3632
#define NCLS   128
#define ROWB   80
#define STAGE_B (2 * BM * ROWB)          // 20480
#define NSTG   4
#define SM_STAGES (NSTG * STAGE_B)       // 81920
#define SM_ZRED   (SM_STAGES + 512)
#define SM_CZ     (SM_ZRED + 1024)
#define SM_TOTAL  (SM_CZ + 2048)         // 85504

// ---------------- device scratch ----------------
__device__ __nv_bfloat16 g_hi[3 * Bsz * Dh];
__device__ int   g_hist[256];
__device__ float g_P[3][NCLS][Dh];
__device__ float g_Zss[T32 * Bsz];
__device__ float g_Ztt[2][T32 * Bsz];
__device__ float g_Zxh[2][T32 * Bsz];
__device__ float g_Zxt[2][T32 * Bsz];
__device__ double g_bsum[256];
__device__ int    g_cnt;

// ---------------- PTX helpers (family-generic) ----------------
__device__ __forceinline__ uint32_t smem_u32(const void* p) {
    uint32_t a;
    asm("{ .reg .u64 t; cvta.to.shared.u64 t, %1; cvt.u32.u64 %0, t; }" : "=r"(a) : "l"(p));
    return a;
}
__device__ __forceinline__ void cp16(uint32_t dst, const void* src) {
    asm volatile("cp.async.cg.shared.global [%0], [%1], 16;" :: "r"(dst), "l"(src));
}
__device__ __forceinline__ void cp_commit() { asm volatile("cp.async.commit_group;"); }
__device__ __forceinline__ void cp_wait2()  { asm volatile("cp.async.wait_group 2;"); }
__device__ __forceinline__ void ldm4(uint32_t& r0, uint32_t& r1, uint32_t& r2,
                                     uint32_t& r3, uint32_t addr) {
    asm volatile("ldmatrix.sync.aligned.m8n8.x4.shared.b16 {%0,%1,%2,%3}, [%4];"
                 : "=r"(r0), "=r"(r1), "=r"(r2), "=r"(r3) : "r"(addr));
}
__device__ __forceinline__ void mma16816(float* c, const uint32_t* a,
                                         uint32_t b0, uint32_t b1) {
    asm volatile("mma.sync.aligned.m16n8k16.row.col.f32.bf16.bf16.f32 "
                 "{%0,%1,%2,%3}, {%4,%5,%6,%7}, {%8,%9}, {%0,%1,%2,%3};"
                 : "+f"(c[0]), "+f"(c[1]), "+f"(c[2]), "+f"(c[3])
                 : "r"(a[0]), "r"(a[1]), "r"(a[2]), "r"(a[3]), "r"(b0), "r"(b1));
}

// --- 1) prep node: norm blocks (0-191), hist (192), class sums (193-576) ---
__global__ void __launch_bounds__(256, 2)
prep_k(const float* __restrict__ hs, const float* __restrict__ t0,
       const float* __restrict__ t1, const int* __restrict__ labels) {
    const int tid = threadIdx.x;
    if (blockIdx.x == 192) {             // label histogram
        __shared__ int h[256];
        h[tid] = 0;
        __syncthreads();
        for (int i = tid; i < Bsz; i += 256) atomicAdd(&h[labels[i] & 255], 1);
        __syncthreads();
        g_hist[tid] = h[tid];
        return;
    }
    if (blockIdx.x >= 193) {             // class-sum block (set, cls)
        int b = blockIdx.x - 193;
        int set = b >> 7;                // 0..2
        int cls = b & (NCLS - 1);
        const float* src = (set == 0) ? hs : (set == 1) ? t0 : t1;
        __shared__ int   slab[Bsz];
        __shared__ float sp[8][Dh];
        for (int j = tid; j < Bsz; j += 256) slab[j] = labels[j];
        __syncthreads();
        const int grp = tid >> 5, dthr = tid & 31;   // warp-group, dim lane
        float acc[8];
        #pragma unroll
        for (int i = 0; i < 8; ++i) acc[i] = 0.f;
        for (int j = grp * 512; j < grp * 512 + 512; ++j) {
            if (slab[j] != cls) continue;            // warp-uniform branch
            const float4* p = reinterpret_cast<const float4*>(src + j * Dh)
                              + dthr * 2;
            float4 a = p[0], bq = p[1];
            float x[8] = {a.x, a.y, a.z, a.w, bq.x, bq.y, bq.z, bq.w};
            float ss = 0.f;
            #pragma unroll
            for (int i = 0; i < 8; ++i) ss += x[i] * x[i];
            #pragma unroll
            for (int o = 16; o; o >>= 1)
                ss += __shfl_xor_sync(0xffffffffu, ss, o);
            float inv = 1.0f / fmaxf(sqrtf(ss), 1e-12f);
            #pragma unroll
            for (int i = 0; i < 8; ++i)
                acc[i] += __bfloat162float(__float2bfloat16(x[i] * inv));
        }
        #pragma unroll
        for (int i = 0; i < 8; ++i) sp[grp][dthr * 8 + i] = acc[i];
        __syncthreads();
        float s = 0.f;                               // fixed order g=0..7
        #pragma unroll
        for (int g = 0; g < 8; ++g) s += sp[g][tid];
        g_P[set][cls][tid] = s;
        return;
    }
    // norm block: 8 rows/warp, 16 loads in flight
    const int w = tid >> 5, lane = tid & 31;
    const int which = blockIdx.x >> 6;
    const int row0 = ((blockIdx.x & 63) << 6) + (w << 3);
    const float* src = (which == 0) ? hs : (which == 1) ? t0 : t1;

    float4 v[8][2];
    #pragma unroll
    for (int q = 0; q < 8; ++q) {
        const float4* p = reinterpret_cast<const float4*>(src + (row0 + q) * Dh)
                          + lane * 2;
        v[q][0] = p[0];
        v[q][1] = p[1];
    }
    #pragma unroll
    for (int q = 0; q < 8; ++q) {
        float x[8] = {v[q][0].x, v[q][0].y, v[q][0].z, v[q][0].w,
                      v[q][1].x, v[q][1].y, v[q][1].z, v[q][1].w};
        float ss = 0.f;
        #pragma unroll
        for (int i = 0; i < 8; ++i) ss += x[i] * x[i];
        #pragma unroll
        for (int o = 16; o; o >>= 1) ss += __shfl_xor_sync(0xffffffffu, ss, o);
        float inv = 1.0f / fmaxf(sqrtf(ss), 1e-12f);
        __nv_bfloat162 h2[4];
        #pragma unroll
        for (int i = 0; i < 4; ++i)
            h2[i] = __nv_bfloat162(__float2bfloat16(x[2*i]   * inv),
                                   __float2bfloat16(x[2*i+1] * inv));
        reinterpret_cast<uint4*>(g_hi + (which * Bsz + row0 + q) * Dh)[lane] =
            *reinterpret_cast<uint4*>(h2);
    }
}

// ------ 2) deduped bf16 mma GEMM: Z-only epilogue --------------------------
extern __shared__ char smem[];

__global__ void __launch_bounds__(256, 2)
contrast_gemm() {
    int id = blockIdx.x;
    int type, bi, bj;
    if (id < 3 * NBLK_SYM) {
        type = id / NBLK_SYM;
        int r = id - type * NBLK_SYM;
        int b = 0;
        while (r >= T32 - b) { r -= T32 - b; ++b; }
        bi = b; bj = b + r;
    } else {
        int id2 = id - 3 * NBLK_SYM;
        type = 3 + (id2 >> 10);
        bi = (id2 & 1023) >> 5;
        bj = id2 & 31;
    }
    const bool sym = (type < 3);
    const int t = (type == 2 || type == 4) ? 1 : 0;

    const __nv_bfloat16* hsp = g_hi;
    const __nv_bfloat16* htp = g_hi + (1 + t) * Bsz * Dh;
    const __nv_bfloat16* Ap;
    const __nv_bfloat16* Bp;
    float *rowZ, *colZ;
    if (type == 0) {
        Ap = hsp + bi * BM * Dh;  Bp = hsp + bj * BN * Dh;
        rowZ = g_Zss; colZ = g_Zss;
    } else if (sym) {
        Ap = htp + bi * BM * Dh;  Bp = htp + bj * BN * Dh;
        rowZ = g_Ztt[t]; colZ = g_Ztt[t];
    } else {
        Ap = hsp + bi * BM * Dh;  Bp = htp + bj * BN * Dh;
        rowZ = g_Zxh[t]; colZ = g_Zxt[t];
    }
    rowZ += bj * Bsz + bi * BM;
    colZ += bi * Bsz + bj * BN;
    const bool diagblk = sym && (bi == bj);
    const bool do_col = !diagblk;

    const int tid = threadIdx.x;
    const int wid = tid >> 5, lid = tid & 31;
    const uint32_t sb = smem_u32(smem);

    const int cr = tid >> 2, cc = tid & 3;
    auto load_tile = [&](int kk, int stage) {
        uint32_t dst = sb + stage * STAGE_B;
        const __nv_bfloat16* ga = Ap + cr * Dh + kk + cc * 8;
        const __nv_bfloat16* gb = Bp + cr * Dh + kk + cc * 8;
        cp16(dst + cr * ROWB + cc * 16,                    ga);
        cp16(dst + (cr + 64) * ROWB + cc * 16,             ga + 64 * Dh);
        cp16(dst + BM * ROWB + cr * ROWB + cc * 16,        gb);
        cp16(dst + BM * ROWB + (cr + 64) * ROWB + cc * 16, gb + 64 * Dh);
    };

    load_tile(0, 0);
    cp_commit();
    load_tile(BK, 1);
    cp_commit();
    load_tile(2 * BK, 2);
    cp_commit();

    const int wr = wid & 3, wc = wid >> 2;
    const int lrow = lid & 15;
    const int koff = (lid & 16) ? 16 : 0;

    float c[2][8][4];
    #pragma unroll
    for (int mi = 0; mi < 2; ++mi)
        #pragma unroll
        for (int ni = 0; ni < 8; ++ni)
            #pragma unroll
            for (int e = 0; e < 4; ++e) c[mi][ni][e] = 0.f;

    for (int k = 0; k < NK; ++k) {
        cp_wait2();
        __syncthreads();
        if (k + 3 < NK) load_tile((k + 3) * BK, (k + 3) & 3);
        cp_commit();

        uint32_t sA = sb + (k & 3) * STAGE_B;
        uint32_t sB = sA + BM * ROWB;

        #pragma unroll
        for (int ks = 0; ks < 2; ++ks) {
            uint32_t a[2][4], b[4][4];
            #pragma unroll
            for (int mi = 0; mi < 2; ++mi)
                ldm4(a[mi][0], a[mi][1], a[mi][2], a[mi][3],
                     sA + (32 * wr + 16 * mi + lrow) * ROWB + ks * 32 + koff);
            #pragma unroll
            for (int nj = 0; nj < 4; ++nj)
                ldm4(b[nj][0], b[nj][1], b[nj][2], b[nj][3],
                     sB + (64 * wc + 16 * nj + lrow) * ROWB + ks * 32 + koff);
            #pragma unroll
            for (int mi = 0; mi < 2; ++mi)
                #pragma unroll
                for (int ni = 0; ni < 8; ++ni) {
                    int nj = ni >> 1, h = ni & 1;
                    mma16816(c[mi][ni], a[mi], b[nj][h], b[nj][2 + h]);
                }
        }
    }

    // ---- Z-only epilogue (diagonal of sym diag tiles skipped) ----
    float* s_z  = reinterpret_cast<float*>(smem + SM_ZRED);
    float* s_cz = reinterpret_cast<float*>(smem + SM_CZ);

    float zk[4], czp[16];
    #pragma unroll
    for (int q = 0; q < 4; ++q) zk[q] = 0.f;
    #pragma unroll
    for (int q = 0; q < 16; ++q) czp[q] = 0.f;

    #pragma unroll
    for (int mi = 0; mi < 2; ++mi)
        #pragma unroll
        for (int ni = 0; ni < 8; ++ni)
            #pragma unroll
            for (int e = 0; e < 4; ++e) {
                int q = mi * 2 + (e >> 1);
                int p = e & 1;
                int rloc = 32 * wr + (lid >> 2) + 8 * q;
                int col  = 64 * wc + 8 * ni + (lid & 3) * 2 + p;
                if (diagblk && rloc == col) continue;
                float ex = __expf(c[mi][ni][e] * TEMP_INV);
                zk[q] += ex;
                czp[ni * 2 + p] += ex;
            }

    #pragma unroll
    for (int q = 0; q < 4; ++q) {
        #pragma unroll
        for (int o = 1; o < 4; o <<= 1)
            zk[q] += __shfl_xor_sync(0xffffffffu, zk[q], o);
    }
    if ((lid & 3) == 0) {
        #pragma unroll
        for (int q = 0; q < 4; ++q)
            s_z[(32 * wr + (lid >> 2) + 8 * q) * 2 + wc] = zk[q];
    }

    if (do_col) {
        #pragma unroll
        for (int q = 0; q < 16; ++q) {
            #pragma unroll
            for (int o = 4; o < 32; o <<= 1)
                czp[q] += __shfl_xor_sync(0xffffffffu, czp[q], o);
        }
        if (lid < 4) {
            #pragma unroll
            for (int q = 0; q < 16; ++q) {
                int col = 64 * wc + 8 * (q >> 1) + lid * 2 + (q & 1);
                s_cz[col * 4 + wr] = czp[q];
            }
        }
    }
    __syncthreads();

    if (tid < BM) {
        rowZ[tid] = s_z[tid * 2] + s_z[tid * 2 + 1];
        if (do_col)
            colZ[tid] = s_cz[tid * 4] + s_cz[tid * 4 + 1]
                      + s_cz[tid * 4 + 2] + s_cz[tid * 4 + 3];
    }
}

// --- 3) finalize: Z assembly + S via class-sum dots + global mean ----------
__global__ void finalize_k(const int* __restrict__ labels,
                           float* __restrict__ out) {
    const int tid = threadIdx.x;
    const int g = blockIdx.x * 64 + (tid >> 2);   // row 0..16383
    const int q = tid & 3;
    const int t = g >> 13;
    const int i = g & (NROW - 1);
    const int cls = labels[i & (Bsz - 1)] & (NCLS - 1);

    float Z = 0.f;
    const __nv_bfloat16* xrow;
    if (i < Bsz) {
        #pragma unroll
        for (int k = 0; k < 8; ++k) {
            int c = q * 8 + k;
            Z += g_Zss[c * Bsz + i] + g_Zxh[t][c * Bsz + i];
        }
        xrow = g_hi + i * Dh;
    } else {
        int ii = i - Bsz;
        #pragma unroll
        for (int k = 0; k < 8; ++k) {
            int c = q * 8 + k;
            Z += g_Ztt[t][c * Bsz + ii] + g_Zxt[t][c * Bsz + ii];
        }
        xrow = g_hi + (1 + t) * Bsz * Dh + ii * Dh;
    }

    // dot(x, P_hs[c]+P_ht[c]) and self-dot over dims q*64..q*64+63
    const float* P0 = g_P[0][cls]     + q * 64;
    const float* P1 = g_P[1 + t][cls] + q * 64;
    float dot = 0.f, self = 0.f;
    #pragma unroll
    for (int b = 0; b < 4; ++b) {
        uint4 xb = reinterpret_cast<const uint4*>(xrow + q * 64)[b * 2];
        uint4 xb2 = reinterpret_cast<const uint4*>(xrow + q * 64)[b * 2 + 1];
        const __nv_bfloat16* xp = reinterpret_cast<const __nv_bfloat16*>(&xb);
        const __nv_bfloat16* xp2 = reinterpret_cast<const __nv_bfloat16*>(&xb2);
        #pragma unroll
        for (int d2 = 0; d2 < 8; ++d2) {
            float xv = __bfloat162float(xp[d2]);
            float pv = P0[b * 16 + d2] + P1[b * 16 + d2];
            dot  += xv * pv;
            self += xv * xv;
        }
        #pragma unroll
        for (int d2 = 0; d2 < 8; ++d2) {
            float xv = __bfloat162float(xp2[d2]);
            float pv = P0[b * 16 + 8 + d2] + P1[b * 16 + 8 + d2];
            dot  += xv * pv;
            self += xv * xv;
        }
    }

    #pragma unroll
    for (int o = 1; o < 4; o <<= 1) {
        Z    += __shfl_xor_sync(0xffffffffu, Z, o);
        dot  += __shfl_xor_sync(0xffffffffu, dot, o);
        self += __shfl_xor_sync(0xffffffffu, self, o);
    }

    double acc = 0.0;
    if (q == 0) {
        int M = 2 * g_hist[labels[i & (Bsz - 1)] & 255] - 1;
        float S = (dot - self) * TEMP_INV;
        acc = (double)(logf(Z) - S / (float)M);
    }
    #pragma unroll
    for (int o = 16; o; o >>= 1) acc += __shfl_xor_sync(0xffffffffu, acc, o);

    __shared__ double ws[8];
    const int lid = tid & 31, wid = tid >> 5;
    if (lid == 0) ws[wid] = acc;
    __syncthreads();
    if (tid == 0) {
        double s = 0.0;
        #pragma unroll
        for (int k = 0; k < 8; ++k) s += ws[k];
        g_bsum[blockIdx.x] = s;
    }

    __shared__ int is_last;
    if (tid == 0) {
        __threadfence();
        is_last = (atomicAdd(&g_cnt, 1) == gridDim.x - 1);
    }
    __syncthreads();
    if (is_last) {
        double a2 = (tid < 256) ? g_bsum[tid] : 0.0;
        #pragma unroll
        for (int o = 16; o; o >>= 1) a2 += __shfl_xor_sync(0xffffffffu, a2, o);
        if (lid == 0) ws[wid] = a2;
        __syncthreads();
        if (tid == 0) {
            double s = 0.0;
            #pragma unroll
            for (int k = 0; k < 8; ++k) s += ws[k];
            out[0] = (float)(s / (double)(2 * NROW));
            g_cnt = 0;
        }
    }
}

// ---------------- launch ----------------
extern "C" void kernel_launch(void* const* d_in, const int* in_sizes, int n_in,
                              void* d_out, int out_size) {
    const float* hs     = (const float*)d_in[0];
    const float* ht0    = (const float*)d_in[1];
    const float* ht1    = (const float*)d_in[2];
    const int*   labels = (const int*)d_in[3];
    float*       out    = (float*)d_out;
    (void)in_sizes; (void)n_in; (void)out_size;

    prep_k<<<193 + 3 * NCLS, 256>>>(hs, ht0, ht1, labels);

    cudaFuncSetAttribute(contrast_gemm,
                         cudaFuncAttributeMaxDynamicSharedMemorySize, SM_TOTAL);
    contrast_gemm<<<NBLK_TOTAL, 256, SM_TOTAL>>>();

    finalize_k<<<256, 256>>>(labels, out);
}

// round 16
// speedup vs baseline: 1.3734x; 1.3734x over previous
#include <cuda_runtime.h>
#include <cuda_bf16.h>
#include <math.h>
#include <stdint.h>

#define Bsz    4096
#define Dh     256
#define NROW   8192
#define TEMP_INV 10.0f
#define EXPK   14.4269504088896f        // TEMP_INV * log2(e)
#define BM     128
#define BN     128
#define BK     32
#define NK     8
#define T32    32
#define NBLK_SYM   528
#define NBLK_TOTAL (3 * NBLK_SYM + 2 * 1024)   // 3632
#define ROWB   80
#define STAGE_B (2 * BM * ROWB)          // 20480
#define NSTG   4
#define SM_STAGES (NSTG * STAGE_B)       // 81920
#define SM_CLAB   SM_STAGES
#define SM_ZRED   (SM_CLAB + 512)
#define SM_SRED   (SM_ZRED + 1024)
#define SM_CZ     (SM_SRED + 1024)
#define SM_CS     (SM_CZ + 2048)
#define SM_TOTAL  (SM_CS + 2048)         // 88576

// ---------------- device scratch ----------------
__device__ __nv_bfloat16 g_hi[3 * Bsz * Dh];
__device__ int   g_hist[256];
__device__ float g_Zss[T32 * Bsz],      g_Sss[T32 * Bsz];
__device__ float g_Ztt[2][T32 * Bsz],   g_Stt[2][T32 * Bsz];
__device__ float g_Zxh[2][T32 * Bsz],   g_Sxh[2][T32 * Bsz];
__device__ float g_Zxt[2][T32 * Bsz],   g_Sxt[2][T32 * Bsz];
__device__ double g_bsum[256];
__device__ int    g_cnt;

// ---------------- PTX helpers (family-generic) ----------------
__device__ __forceinline__ uint32_t smem_u32(const void* p) {
    uint32_t a;
    asm("{ .reg .u64 t; cvta.to.shared.u64 t, %1; cvt.u32.u64 %0, t; }" : "=r"(a) : "l"(p));
    return a;
}
__device__ __forceinline__ void cp16(uint32_t dst, const void* src) {
    asm volatile("cp.async.cg.shared.global [%0], [%1], 16;" :: "r"(dst), "l"(src));
}
__device__ __forceinline__ void cp_commit() { asm volatile("cp.async.commit_group;"); }
__device__ __forceinline__ void cp_wait2()  { asm volatile("cp.async.wait_group 2;"); }
__device__ __forceinline__ void ldm4(uint32_t& r0, uint32_t& r1, uint32_t& r2,
                                     uint32_t& r3, uint32_t addr) {
    asm volatile("ldmatrix.sync.aligned.m8n8.x4.shared.b16 {%0,%1,%2,%3}, [%4];"
                 : "=r"(r0), "=r"(r1), "=r"(r2), "=r"(r3) : "r"(addr));
}
__device__ __forceinline__ void mma16816(float* c, const uint32_t* a,
                                         uint32_t b0, uint32_t b1) {
    asm volatile("mma.sync.aligned.m16n8k16.row.col.f32.bf16.bf16.f32 "
                 "{%0,%1,%2,%3}, {%4,%5,%6,%7}, {%8,%9}, {%0,%1,%2,%3};"
                 : "+f"(c[0]), "+f"(c[1]), "+f"(c[2]), "+f"(c[3])
                 : "r"(a[0]), "r"(a[1]), "r"(a[2]), "r"(a[3]), "r"(b0), "r"(b1));
}

// --- 1) normalize + bf16 round: 8 rows/warp; last block: hist --------------
__global__ void __launch_bounds__(256, 2)
prep_k(const float* __restrict__ hs, const float* __restrict__ t0,
       const float* __restrict__ t1, const int* __restrict__ labels) {
    if (blockIdx.x == 192) {
        __shared__ int h[256];
        int t = threadIdx.x;
        h[t] = 0;
        __syncthreads();
        for (int i = t; i < Bsz; i += 256) atomicAdd(&h[labels[i] & 255], 1);
        __syncthreads();
        g_hist[t] = h[t];
        return;
    }
    const int w = threadIdx.x >> 5, lane = threadIdx.x & 31;
    const int which = blockIdx.x >> 6;
    const int row0 = ((blockIdx.x & 63) << 6) + (w << 3);
    const float* src = (which == 0) ? hs : (which == 1) ? t0 : t1;

    float4 v[8][2];
    #pragma unroll
    for (int q = 0; q < 8; ++q) {
        const float4* p = reinterpret_cast<const float4*>(src + (row0 + q) * Dh)
                          + lane * 2;
        v[q][0] = p[0];
        v[q][1] = p[1];
    }
    #pragma unroll
    for (int q = 0; q < 8; ++q) {
        float x[8] = {v[q][0].x, v[q][0].y, v[q][0].z, v[q][0].w,
                      v[q][1].x, v[q][1].y, v[q][1].z, v[q][1].w};
        float ss = 0.f;
        #pragma unroll
        for (int i = 0; i < 8; ++i) ss += x[i] * x[i];
        #pragma unroll
        for (int o = 16; o; o >>= 1) ss += __shfl_xor_sync(0xffffffffu, ss, o);
        float inv = 1.0f / fmaxf(sqrtf(ss), 1e-12f);
        __nv_bfloat162 h2[4];
        #pragma unroll
        for (int i = 0; i < 4; ++i)
            h2[i] = __nv_bfloat162(__float2bfloat16(x[2*i]   * inv),
                                   __float2bfloat16(x[2*i+1] * inv));
        reinterpret_cast<uint4*>(g_hi + (which * Bsz + row0 + q) * Dh)[lane] =
            *reinterpret_cast<uint4*>(h2);
    }
}

// ------ 3) deduped bf16 mma GEMM: 4-stage pipeline, lean epilogue ----------
extern __shared__ char smem[];

__global__ void __launch_bounds__(256, 2)
contrast_gemm(const int* __restrict__ labels) {
    int id = blockIdx.x;
    int type, bi, bj;
    if (id < 3 * NBLK_SYM) {
        type = id / NBLK_SYM;
        int r = id - type * NBLK_SYM;
        int b = 0;
        while (r >= T32 - b) { r -= T32 - b; ++b; }
        bi = b; bj = b + r;
    } else {
        int id2 = id - 3 * NBLK_SYM;
        type = 3 + (id2 >> 10);
        bi = (id2 & 1023) >> 5;
        bj = id2 & 31;
    }
    const bool sym = (type < 3);
    const int t = (type == 2 || type == 4) ? 1 : 0;

    const __nv_bfloat16* hsp = g_hi;
    const __nv_bfloat16* htp = g_hi + (1 + t) * Bsz * Dh;
    const __nv_bfloat16* Ap;
    const __nv_bfloat16* Bp;
    float *rowZ, *rowS, *colZ, *colS;
    if (type == 0) {
        Ap = hsp + bi * BM * Dh;  Bp = hsp + bj * BN * Dh;
        rowZ = g_Zss; rowS = g_Sss; colZ = g_Zss; colS = g_Sss;
    } else if (sym) {
        Ap = htp + bi * BM * Dh;  Bp = htp + bj * BN * Dh;
        rowZ = g_Ztt[t]; rowS = g_Stt[t]; colZ = g_Ztt[t]; colS = g_Stt[t];
    } else {
        Ap = hsp + bi * BM * Dh;  Bp = htp + bj * BN * Dh;
        rowZ = g_Zxh[t]; rowS = g_Sxh[t]; colZ = g_Zxt[t]; colS = g_Sxt[t];
    }
    rowZ += bj * Bsz + bi * BM;  rowS += bj * Bsz + bi * BM;
    colZ += bi * Bsz + bj * BN;  colS += bi * Bsz + bj * BN;
    const bool diagblk = sym && (bi == bj);
    const bool do_col = !diagblk;

    const int tid = threadIdx.x;
    const int wid = tid >> 5, lid = tid & 31;
    const uint32_t sb = smem_u32(smem);

    if (tid < BN)
        *reinterpret_cast<int*>(smem + SM_CLAB + tid * 4) = labels[bj * BN + tid];

    const int cr = tid >> 2, cc = tid & 3;
    auto load_tile = [&](int kk, int stage) {
        uint32_t dst = sb + stage * STAGE_B;
        const __nv_bfloat16* ga = Ap + cr * Dh + kk + cc * 8;
        const __nv_bfloat16* gb = Bp + cr * Dh + kk + cc * 8;
        cp16(dst + cr * ROWB + cc * 16,                    ga);
        cp16(dst + (cr + 64) * ROWB + cc * 16,             ga + 64 * Dh);
        cp16(dst + BM * ROWB + cr * ROWB + cc * 16,        gb);
        cp16(dst + BM * ROWB + (cr + 64) * ROWB + cc * 16, gb + 64 * Dh);
    };

    load_tile(0, 0);
    cp_commit();
    load_tile(BK, 1);
    cp_commit();
    load_tile(2 * BK, 2);
    cp_commit();

    const int wr = wid & 3, wc = wid >> 2;
    const int lrow = lid & 15;
    const int koff = (lid & 16) ? 16 : 0;

    float c[2][8][4];
    #pragma unroll
    for (int mi = 0; mi < 2; ++mi)
        #pragma unroll
        for (int ni = 0; ni < 8; ++ni)
            #pragma unroll
            for (int e = 0; e < 4; ++e) c[mi][ni][e] = 0.f;

    for (int k = 0; k < NK; ++k) {
        cp_wait2();
        __syncthreads();
        if (k + 3 < NK) load_tile((k + 3) * BK, (k + 3) & 3);
        cp_commit();

        uint32_t sA = sb + (k & 3) * STAGE_B;
        uint32_t sB = sA + BM * ROWB;

        #pragma unroll
        for (int ks = 0; ks < 2; ++ks) {
            uint32_t a[2][4], b[4][4];
            #pragma unroll
            for (int mi = 0; mi < 2; ++mi)
                ldm4(a[mi][0], a[mi][1], a[mi][2], a[mi][3],
                     sA + (32 * wr + 16 * mi + lrow) * ROWB + ks * 32 + koff);
            #pragma unroll
            for (int nj = 0; nj < 4; ++nj)
                ldm4(b[nj][0], b[nj][1], b[nj][2], b[nj][3],
                     sB + (64 * wc + 16 * nj + lrow) * ROWB + ks * 32 + koff);
            #pragma unroll
            for (int mi = 0; mi < 2; ++mi)
                #pragma unroll
                for (int ni = 0; ni < 8; ++ni) {
                    int nj = ni >> 1, h = ni & 1;
                    mma16816(c[mi][ni], a[mi], b[nj][h], b[nj][2 + h]);
                }
        }
    }

    // ---- lean epilogue: exp2 with folded scale, raw-sim masked sums ----
    const int* clab = reinterpret_cast<const int*>(smem + SM_CLAB);
    float* s_z  = reinterpret_cast<float*>(smem + SM_ZRED);
    float* s_s  = reinterpret_cast<float*>(smem + SM_SRED);
    float* s_cz = reinterpret_cast<float*>(smem + SM_CZ);
    float* s_cs = reinterpret_cast<float*>(smem + SM_CS);

    int rlab[4];
    #pragma unroll
    for (int q = 0; q < 4; ++q)
        rlab[q] = labels[bi * BM + 32 * wr + (lid >> 2) + 8 * q];

    float zk[4], sk[4], czp[16], csp[16];
    #pragma unroll
    for (int q = 0; q < 4; ++q) { zk[q] = 0.f; sk[q] = 0.f; }
    #pragma unroll
    for (int q = 0; q < 16; ++q) { czp[q] = 0.f; csp[q] = 0.f; }

    #pragma unroll
    for (int mi = 0; mi < 2; ++mi)
        #pragma unroll
        for (int ni = 0; ni < 8; ++ni)
            #pragma unroll
            for (int e = 0; e < 4; ++e) {
                int q = mi * 2 + (e >> 1);
                int p = e & 1;
                int rloc = 32 * wr + (lid >> 2) + 8 * q;
                int col  = 64 * wc + 8 * ni + (lid & 3) * 2 + p;
                if (diagblk && rloc == col) continue;   // exact diagonal mask
                float cv = c[mi][ni][e];
                float ex = exp2f(cv * EXPK);            // exp(cv*TEMP_INV)
                zk[q] += ex;
                czp[ni * 2 + p] += ex;
                if (clab[col] == rlab[q]) { sk[q] += cv; csp[ni * 2 + p] += cv; }
            }

    #pragma unroll
    for (int q = 0; q < 4; ++q) {
        #pragma unroll
        for (int o = 1; o < 4; o <<= 1) {
            zk[q] += __shfl_xor_sync(0xffffffffu, zk[q], o);
            sk[q] += __shfl_xor_sync(0xffffffffu, sk[q], o);
        }
    }
    if ((lid & 3) == 0) {
        #pragma unroll
        for (int q = 0; q < 4; ++q) {
            int row = 32 * wr + (lid >> 2) + 8 * q;
            s_z[row * 2 + wc] = zk[q];
            s_s[row * 2 + wc] = sk[q] * TEMP_INV;   // scale once
        }
    }

    if (do_col) {
        #pragma unroll
        for (int q = 0; q < 16; ++q) {
            #pragma unroll
            for (int o = 4; o < 32; o <<= 1) {
                czp[q] += __shfl_xor_sync(0xffffffffu, czp[q], o);
                csp[q] += __shfl_xor_sync(0xffffffffu, csp[q], o);
            }
        }
        if (lid < 4) {
            #pragma unroll
            for (int q = 0; q < 16; ++q) {
                int col = 64 * wc + 8 * (q >> 1) + lid * 2 + (q & 1);
                s_cz[col * 4 + wr] = czp[q];
                s_cs[col * 4 + wr] = csp[q] * TEMP_INV;   // scale once
            }
        }
    }
    __syncthreads();

    if (tid < BM) {
        rowZ[tid] = s_z[tid * 2] + s_z[tid * 2 + 1];
        rowS[tid] = s_s[tid * 2] + s_s[tid * 2 + 1];
        if (do_col) {
            colZ[tid] = s_cz[tid * 4] + s_cz[tid * 4 + 1]
                      + s_cz[tid * 4 + 2] + s_cz[tid * 4 + 3];
            colS[tid] = s_cs[tid * 4] + s_cs[tid * 4 + 1]
                      + s_cs[tid * 4 + 2] + s_cs[tid * 4 + 3];
        }
    }
}

// --- 4) fused finalize: per-row loss + global mean -------------------------
__global__ void finalize_k(const int* __restrict__ labels,
                           float* __restrict__ out) {
    const int tid = threadIdx.x;
    const int g = blockIdx.x * 64 + (tid >> 2);
    const int q = tid & 3;
    const int t = g >> 13;
    const int i = g & (NROW - 1);

    float Z = 0.f, S = 0.f;
    if (i < Bsz) {
        #pragma unroll
        for (int k = 0; k < 8; ++k) {
            int c = q * 8 + k;
            Z += g_Zss[c * Bsz + i] + g_Zxh[t][c * Bsz + i];
            S += g_Sss[c * Bsz + i] + g_Sxh[t][c * Bsz + i];
        }
    } else {
        int ii = i - Bsz;
        #pragma unroll
        for (int k = 0; k < 8; ++k) {
            int c = q * 8 + k;
            Z += g_Ztt[t][c * Bsz + ii] + g_Zxt[t][c * Bsz + ii];
            S += g_Stt[t][c * Bsz + ii] + g_Sxt[t][c * Bsz + ii];
        }
    }
    #pragma unroll
    for (int o = 1; o < 4; o <<= 1) {
        Z += __shfl_xor_sync(0xffffffffu, Z, o);
        S += __shfl_xor_sync(0xffffffffu, S, o);
    }

    double acc = 0.0;
    if (q == 0) {
        int M = 2 * g_hist[labels[i & (Bsz - 1)] & 255] - 1;
        acc = (double)(logf(Z) - S / (float)M);
    }
    #pragma unroll
    for (int o = 16; o; o >>= 1) acc += __shfl_xor_sync(0xffffffffu, acc, o);

    __shared__ double ws[8];
    const int lid = tid & 31, wid = tid >> 5;
    if (lid == 0) ws[wid] = acc;
    __syncthreads();
    if (tid == 0) {
        double s = 0.0;
        #pragma unroll
        for (int k = 0; k < 8; ++k) s += ws[k];
        g_bsum[blockIdx.x] = s;
    }

    __shared__ int is_last;
    if (tid == 0) {
        __threadfence();
        is_last = (atomicAdd(&g_cnt, 1) == gridDim.x - 1);
    }
    __syncthreads();
    if (is_last) {
        double a2 = (tid < 256) ? g_bsum[tid] : 0.0;
        #pragma unroll
        for (int o = 16; o; o >>= 1) a2 += __shfl_xor_sync(0xffffffffu, a2, o);
        if (lid == 0) ws[wid] = a2;
        __syncthreads();
        if (tid == 0) {
            double s = 0.0;
            #pragma unroll
            for (int k = 0; k < 8; ++k) s += ws[k];
            out[0] = (float)(s / (double)(2 * NROW));
            g_cnt = 0;
        }
    }
}

// ---------------- launch ----------------
extern "C" void kernel_launch(void* const* d_in, const int* in_sizes, int n_in,
                              void* d_out, int out_size) {
    const float* hs     = (const float*)d_in[0];
    const float* ht0    = (const float*)d_in[1];
    const float* ht1    = (const float*)d_in[2];
    const int*   labels = (const int*)d_in[3];
    float*       out    = (float*)d_out;
    (void)in_sizes; (void)n_in; (void)out_size;

    prep_k<<<193, 256>>>(hs, ht0, ht1, labels);

    cudaFuncSetAttribute(contrast_gemm,
                         cudaFuncAttributeMaxDynamicSharedMemorySize, SM_TOTAL);
    contrast_gemm<<<NBLK_TOTAL, 256, SM_TOTAL>>>(labels);

    finalize_k<<<256, 256>>>(labels, out);
}

// round 17
// speedup vs baseline: 1.3826x; 1.0067x over previous
#include <cuda_runtime.h>
#include <cuda_bf16.h>
#include <math.h>
#include <stdint.h>

#define Bsz    4096
#define Dh     256
#define NROW   8192
#define TEMP_INV 10.0f
#define EXPK   14.4269504088896f        // TEMP_INV * log2(e)
#define BM     128
#define BN     128
#define BK     32
#define NK     8
#define T32    32
#define NBLK_SYM   528
#define NBLK_TOTAL (3 * NBLK_SYM + 2 * 1024)   // 3632
#define ROWB   80
#define STAGE_B (2 * BM * ROWB)          // 20480
#define NSTG   4
#define SM_STAGES (NSTG * STAGE_B)       // 81920
#define SM_CLAB   SM_STAGES
#define SM_ZRED   (SM_CLAB + 512)
#define SM_SRED   (SM_ZRED + 1024)
#define SM_CZ     (SM_SRED + 1024)
#define SM_CS     (SM_CZ + 2048)
#define SM_TOTAL  (SM_CS + 2048)         // 88576

// ---------------- device scratch ----------------
__device__ __nv_bfloat16 g_hi[3 * Bsz * Dh];
__device__ int   g_hist[256];
__device__ float g_Zss[T32 * Bsz],      g_Sss[T32 * Bsz];
__device__ float g_Ztt[2][T32 * Bsz],   g_Stt[2][T32 * Bsz];
__device__ float g_Zxh[2][T32 * Bsz],   g_Sxh[2][T32 * Bsz];
__device__ float g_Zxt[2][T32 * Bsz],   g_Sxt[2][T32 * Bsz];
__device__ double g_bsum[256];
__device__ int    g_cnt;

// ---------------- PTX helpers (family-generic) ----------------
__device__ __forceinline__ uint32_t smem_u32(const void* p) {
    uint32_t a;
    asm("{ .reg .u64 t; cvta.to.shared.u64 t, %1; cvt.u32.u64 %0, t; }" : "=r"(a) : "l"(p));
    return a;
}
__device__ __forceinline__ void cp16(uint32_t dst, const void* src) {
    asm volatile("cp.async.cg.shared.global [%0], [%1], 16;" :: "r"(dst), "l"(src));
}
__device__ __forceinline__ void cp_commit() { asm volatile("cp.async.commit_group;"); }
__device__ __forceinline__ void cp_wait2()  { asm volatile("cp.async.wait_group 2;"); }
__device__ __forceinline__ void ldm4(uint32_t& r0, uint32_t& r1, uint32_t& r2,
                                     uint32_t& r3, uint32_t addr) {
    asm volatile("ldmatrix.sync.aligned.m8n8.x4.shared.b16 {%0,%1,%2,%3}, [%4];"
                 : "=r"(r0), "=r"(r1), "=r"(r2), "=r"(r3) : "r"(addr));
}
__device__ __forceinline__ void mma16816(float* c, const uint32_t* a,
                                         uint32_t b0, uint32_t b1) {
    asm volatile("mma.sync.aligned.m16n8k16.row.col.f32.bf16.bf16.f32 "
                 "{%0,%1,%2,%3}, {%4,%5,%6,%7}, {%8,%9}, {%0,%1,%2,%3};"
                 : "+f"(c[0]), "+f"(c[1]), "+f"(c[2]), "+f"(c[3])
                 : "r"(a[0]), "r"(a[1]), "r"(a[2]), "r"(a[3]), "r"(b0), "r"(b1));
}
__device__ __forceinline__ void gdc_wait() {
    asm volatile("griddepcontrol.wait;" ::: "memory");
}
__device__ __forceinline__ void gdc_launch() {
    asm volatile("griddepcontrol.launch_dependents;" ::: "memory");
}

// --- 1) normalize + bf16 round: 8 rows/warp; last block: hist --------------
__global__ void __launch_bounds__(256, 2)
prep_k(const float* __restrict__ hs, const float* __restrict__ t0,
       const float* __restrict__ t1, const int* __restrict__ labels) {
    if (blockIdx.x == 192) {
        __shared__ int h[256];
        int t = threadIdx.x;
        h[t] = 0;
        __syncthreads();
        for (int i = t; i < Bsz; i += 256) atomicAdd(&h[labels[i] & 255], 1);
        __syncthreads();
        g_hist[t] = h[t];
        gdc_launch();
        return;
    }
    const int w = threadIdx.x >> 5, lane = threadIdx.x & 31;
    const int which = blockIdx.x >> 6;
    const int row0 = ((blockIdx.x & 63) << 6) + (w << 3);
    const float* src = (which == 0) ? hs : (which == 1) ? t0 : t1;

    float4 v[8][2];
    #pragma unroll
    for (int q = 0; q < 8; ++q) {
        const float4* p = reinterpret_cast<const float4*>(src + (row0 + q) * Dh)
                          + lane * 2;
        v[q][0] = p[0];
        v[q][1] = p[1];
    }
    #pragma unroll
    for (int q = 0; q < 8; ++q) {
        float x[8] = {v[q][0].x, v[q][0].y, v[q][0].z, v[q][0].w,
                      v[q][1].x, v[q][1].y, v[q][1].z, v[q][1].w};
        float ss = 0.f;
        #pragma unroll
        for (int i = 0; i < 8; ++i) ss += x[i] * x[i];
        #pragma unroll
        for (int o = 16; o; o >>= 1) ss += __shfl_xor_sync(0xffffffffu, ss, o);
        float inv = 1.0f / fmaxf(sqrtf(ss), 1e-12f);
        __nv_bfloat162 h2[4];
        #pragma unroll
        for (int i = 0; i < 4; ++i)
            h2[i] = __nv_bfloat162(__float2bfloat16(x[2*i]   * inv),
                                   __float2bfloat16(x[2*i+1] * inv));
        reinterpret_cast<uint4*>(g_hi + (which * Bsz + row0 + q) * Dh)[lane] =
            *reinterpret_cast<uint4*>(h2);
    }
    gdc_launch();
}

// ------ 3) deduped bf16 mma GEMM: 4-stage pipeline, lean epilogue ----------
extern __shared__ char smem[];

__global__ void __launch_bounds__(256, 2)
contrast_gemm(const int* __restrict__ labels) {
    int id = blockIdx.x;
    int type, bi, bj;
    if (id < 3 * NBLK_SYM) {
        type = id / NBLK_SYM;
        int r = id - type * NBLK_SYM;
        int b = 0;
        while (r >= T32 - b) { r -= T32 - b; ++b; }
        bi = b; bj = b + r;
    } else {
        int id2 = id - 3 * NBLK_SYM;
        type = 3 + (id2 >> 10);
        bi = (id2 & 1023) >> 5;
        bj = id2 & 31;
    }
    const bool sym = (type < 3);
    const int t = (type == 2 || type == 4) ? 1 : 0;

    const __nv_bfloat16* hsp = g_hi;
    const __nv_bfloat16* htp = g_hi + (1 + t) * Bsz * Dh;
    const __nv_bfloat16* Ap;
    const __nv_bfloat16* Bp;
    float *rowZ, *rowS, *colZ, *colS;
    if (type == 0) {
        Ap = hsp + bi * BM * Dh;  Bp = hsp + bj * BN * Dh;
        rowZ = g_Zss; rowS = g_Sss; colZ = g_Zss; colS = g_Sss;
    } else if (sym) {
        Ap = htp + bi * BM * Dh;  Bp = htp + bj * BN * Dh;
        rowZ = g_Ztt[t]; rowS = g_Stt[t]; colZ = g_Ztt[t]; colS = g_Stt[t];
    } else {
        Ap = hsp + bi * BM * Dh;  Bp = htp + bj * BN * Dh;
        rowZ = g_Zxh[t]; rowS = g_Sxh[t]; colZ = g_Zxt[t]; colS = g_Sxt[t];
    }
    rowZ += bj * Bsz + bi * BM;  rowS += bj * Bsz + bi * BM;
    colZ += bi * Bsz + bj * BN;  colS += bi * Bsz + bj * BN;
    const bool diagblk = sym && (bi == bj);
    const bool do_col = !diagblk;

    const int tid = threadIdx.x;
    const int wid = tid >> 5, lid = tid & 31;
    const uint32_t sb = smem_u32(smem);

    if (tid < BN)
        *reinterpret_cast<int*>(smem + SM_CLAB + tid * 4) = labels[bj * BN + tid];

    // prep's g_hi writes must be visible before tile loads
    gdc_wait();

    const int cr = tid >> 2, cc = tid & 3;
    auto load_tile = [&](int kk, int stage) {
        uint32_t dst = sb + stage * STAGE_B;
        const __nv_bfloat16* ga = Ap + cr * Dh + kk + cc * 8;
        const __nv_bfloat16* gb = Bp + cr * Dh + kk + cc * 8;
        cp16(dst + cr * ROWB + cc * 16,                    ga);
        cp16(dst + (cr + 64) * ROWB + cc * 16,             ga + 64 * Dh);
        cp16(dst + BM * ROWB + cr * ROWB + cc * 16,        gb);
        cp16(dst + BM * ROWB + (cr + 64) * ROWB + cc * 16, gb + 64 * Dh);
    };

    load_tile(0, 0);
    cp_commit();
    load_tile(BK, 1);
    cp_commit();
    load_tile(2 * BK, 2);
    cp_commit();

    const int wr = wid & 3, wc = wid >> 2;
    const int lrow = lid & 15;
    const int koff = (lid & 16) ? 16 : 0;

    float c[2][8][4];
    #pragma unroll
    for (int mi = 0; mi < 2; ++mi)
        #pragma unroll
        for (int ni = 0; ni < 8; ++ni)
            #pragma unroll
            for (int e = 0; e < 4; ++e) c[mi][ni][e] = 0.f;

    for (int k = 0; k < NK; ++k) {
        cp_wait2();
        __syncthreads();
        if (k + 3 < NK) load_tile((k + 3) * BK, (k + 3) & 3);
        cp_commit();

        uint32_t sA = sb + (k & 3) * STAGE_B;
        uint32_t sB = sA + BM * ROWB;

        #pragma unroll
        for (int ks = 0; ks < 2; ++ks) {
            uint32_t a[2][4], b[4][4];
            #pragma unroll
            for (int mi = 0; mi < 2; ++mi)
                ldm4(a[mi][0], a[mi][1], a[mi][2], a[mi][3],
                     sA + (32 * wr + 16 * mi + lrow) * ROWB + ks * 32 + koff);
            #pragma unroll
            for (int nj = 0; nj < 4; ++nj)
                ldm4(b[nj][0], b[nj][1], b[nj][2], b[nj][3],
                     sB + (64 * wc + 16 * nj + lrow) * ROWB + ks * 32 + koff);
            #pragma unroll
            for (int mi = 0; mi < 2; ++mi)
                #pragma unroll
                for (int ni = 0; ni < 8; ++ni) {
                    int nj = ni >> 1, h = ni & 1;
                    mma16816(c[mi][ni], a[mi], b[nj][h], b[nj][2 + h]);
                }
        }
    }

    // ---- lean epilogue: exp2 with folded scale, raw-sim masked sums ----
    const int* clab = reinterpret_cast<const int*>(smem + SM_CLAB);
    float* s_z  = reinterpret_cast<float*>(smem + SM_ZRED);
    float* s_s  = reinterpret_cast<float*>(smem + SM_SRED);
    float* s_cz = reinterpret_cast<float*>(smem + SM_CZ);
    float* s_cs = reinterpret_cast<float*>(smem + SM_CS);

    int rlab[4];
    #pragma unroll
    for (int q = 0; q < 4; ++q)
        rlab[q] = labels[bi * BM + 32 * wr + (lid >> 2) + 8 * q];

    float zk[4], sk[4], czp[16], csp[16];
    #pragma unroll
    for (int q = 0; q < 4; ++q) { zk[q] = 0.f; sk[q] = 0.f; }
    #pragma unroll
    for (int q = 0; q < 16; ++q) { czp[q] = 0.f; csp[q] = 0.f; }

    #pragma unroll
    for (int mi = 0; mi < 2; ++mi)
        #pragma unroll
        for (int ni = 0; ni < 8; ++ni)
            #pragma unroll
            for (int e = 0; e < 4; ++e) {
                int q = mi * 2 + (e >> 1);
                int p = e & 1;
                int rloc = 32 * wr + (lid >> 2) + 8 * q;
                int col  = 64 * wc + 8 * ni + (lid & 3) * 2 + p;
                if (diagblk && rloc == col) continue;   // exact diagonal mask
                float cv = c[mi][ni][e];
                float ex = exp2f(cv * EXPK);            // exp(cv*TEMP_INV)
                zk[q] += ex;
                czp[ni * 2 + p] += ex;
                if (clab[col] == rlab[q]) { sk[q] += cv; csp[ni * 2 + p] += cv; }
            }

    #pragma unroll
    for (int q = 0; q < 4; ++q) {
        #pragma unroll
        for (int o = 1; o < 4; o <<= 1) {
            zk[q] += __shfl_xor_sync(0xffffffffu, zk[q], o);
            sk[q] += __shfl_xor_sync(0xffffffffu, sk[q], o);
        }
    }
    if ((lid & 3) == 0) {
        #pragma unroll
        for (int q = 0; q < 4; ++q) {
            int row = 32 * wr + (lid >> 2) + 8 * q;
            s_z[row * 2 + wc] = zk[q];
            s_s[row * 2 + wc] = sk[q] * TEMP_INV;   // scale once
        }
    }

    if (do_col) {
        #pragma unroll
        for (int q = 0; q < 16; ++q) {
            #pragma unroll
            for (int o = 4; o < 32; o <<= 1) {
                czp[q] += __shfl_xor_sync(0xffffffffu, czp[q], o);
                csp[q] += __shfl_xor_sync(0xffffffffu, csp[q], o);
            }
        }
        if (lid < 4) {
            #pragma unroll
            for (int q = 0; q < 16; ++q) {
                int col = 64 * wc + 8 * (q >> 1) + lid * 2 + (q & 1);
                s_cz[col * 4 + wr] = czp[q];
                s_cs[col * 4 + wr] = csp[q] * TEMP_INV;   // scale once
            }
        }
    }
    __syncthreads();

    if (tid < BM) {
        rowZ[tid] = s_z[tid * 2] + s_z[tid * 2 + 1];
        rowS[tid] = s_s[tid * 2] + s_s[tid * 2 + 1];
        if (do_col) {
            colZ[tid] = s_cz[tid * 4] + s_cz[tid * 4 + 1]
                      + s_cz[tid * 4 + 2] + s_cz[tid * 4 + 3];
            colS[tid] = s_cs[tid * 4] + s_cs[tid * 4 + 1]
                      + s_cs[tid * 4 + 2] + s_cs[tid * 4 + 3];
        }
    }
    gdc_launch();
}

// --- 4) fused finalize: per-row loss + global mean -------------------------
__global__ void finalize_k(const int* __restrict__ labels,
                           float* __restrict__ out) {
    gdc_wait();                   // all GEMM partials visible
    const int tid = threadIdx.x;
    const int g = blockIdx.x * 64 + (tid >> 2);
    const int q = tid & 3;
    const int t = g >> 13;
    const int i = g & (NROW - 1);

    float Z = 0.f, S = 0.f;
    if (i < Bsz) {
        #pragma unroll
        for (int k = 0; k < 8; ++k) {
            int c = q * 8 + k;
            Z += g_Zss[c * Bsz + i] + g_Zxh[t][c * Bsz + i];
            S += g_Sss[c * Bsz + i] + g_Sxh[t][c * Bsz + i];
        }
    } else {
        int ii = i - Bsz;
        #pragma unroll
        for (int k = 0; k < 8; ++k) {
            int c = q * 8 + k;
            Z += g_Ztt[t][c * Bsz + ii] + g_Zxt[t][c * Bsz + ii];
            S += g_Stt[t][c * Bsz + ii] + g_Sxt[t][c * Bsz + ii];
        }
    }
    #pragma unroll
    for (int o = 1; o < 4; o <<= 1) {
        Z += __shfl_xor_sync(0xffffffffu, Z, o);
        S += __shfl_xor_sync(0xffffffffu, S, o);
    }

    double acc = 0.0;
    if (q == 0) {
        int M = 2 * g_hist[labels[i & (Bsz - 1)] & 255] - 1;
        acc = (double)(logf(Z) - S / (float)M);
    }
    #pragma unroll
    for (int o = 16; o; o >>= 1) acc += __shfl_xor_sync(0xffffffffu, acc, o);

    __shared__ double ws[8];
    const int lid = tid & 31, wid = tid >> 5;
    if (lid == 0) ws[wid] = acc;
    __syncthreads();
    if (tid == 0) {
        double s = 0.0;
        #pragma unroll
        for (int k = 0; k < 8; ++k) s += ws[k];
        g_bsum[blockIdx.x] = s;
    }

    __shared__ int is_last;
    if (tid == 0) {
        __threadfence();
        is_last = (atomicAdd(&g_cnt, 1) == gridDim.x - 1);
    }
    __syncthreads();
    if (is_last) {
        double a2 = (tid < 256) ? g_bsum[tid] : 0.0;
        #pragma unroll
        for (int o = 16; o; o >>= 1) a2 += __shfl_xor_sync(0xffffffffu, a2, o);
        if (lid == 0) ws[wid] = a2;
        __syncthreads();
        if (tid == 0) {
            double s = 0.0;
            #pragma unroll
            for (int k = 0; k < 8; ++k) s += ws[k];
            out[0] = (float)(s / (double)(2 * NROW));
            g_cnt = 0;
        }
    }
}

// ---------------- launch: PDL-chained 3 nodes ----------------
extern "C" void kernel_launch(void* const* d_in, const int* in_sizes, int n_in,
                              void* d_out, int out_size) {
    const float* hs     = (const float*)d_in[0];
    const float* ht0    = (const float*)d_in[1];
    const float* ht1    = (const float*)d_in[2];
    const int*   labels = (const int*)d_in[3];
    float*       out    = (float*)d_out;
    (void)in_sizes; (void)n_in; (void)out_size;

    static bool attr_done = false;
    if (!attr_done) {
        cudaFuncSetAttribute(contrast_gemm,
                             cudaFuncAttributeMaxDynamicSharedMemorySize, SM_TOTAL);
        attr_done = true;
    }

    prep_k<<<193, 256>>>(hs, ht0, ht1, labels);

    cudaLaunchAttribute pdl[1];
    pdl[0].id = cudaLaunchAttributeProgrammaticStreamSerialization;
    pdl[0].val.programmaticStreamSerializationAllowed = 1;

    {
        cudaLaunchConfig_t cfg = {};
        cfg.gridDim = dim3(NBLK_TOTAL, 1, 1);
        cfg.blockDim = dim3(256, 1, 1);
        cfg.dynamicSmemBytes = SM_TOTAL;
        cfg.stream = 0;
        cfg.attrs = pdl;
        cfg.numAttrs = 1;
        cudaLaunchKernelEx(&cfg, contrast_gemm, labels);
    }
    {
        cudaLaunchConfig_t cfg = {};
        cfg.gridDim = dim3(256, 1, 1);
        cfg.blockDim = dim3(256, 1, 1);
        cfg.dynamicSmemBytes = 0;
        cfg.stream = 0;
        cfg.attrs = pdl;
        cfg.numAttrs = 1;
        cudaLaunchKernelEx(&cfg, finalize_k, labels, out);
    }
}